// round 1
// baseline (speedup 1.0000x reference)
#include <cuda_runtime.h>
#include <math.h>

#define KDIM 160
#define HDIM 256
#define TB   128
#define NT   256

// Dynamic smem layout (floats):
//  xs   [160][128]  : x tile transposed (k-major)          20480
//  wsm  [16][132]   : W1 chunk (k-major, padded)            2112
//  qin  [128][4]    : per-row quantum input accum            512
//  trgc [24], trgs[24] : weight-gate trig                      48
#define XS_OFF   0
#define WS_OFF   20480
#define QIN_OFF  (20480 + 2112)
#define TRC_OFF  (QIN_OFF + 512)
#define TRS_OFF  (TRC_OFF + 24)
#define SMEM_FLOATS (TRS_OFF + 24)

// ---------------- quantum gates on 16-amplitude register state ----------------
template<int M>
__device__ __forceinline__ void g_ry(float (&ar)[16], float (&ai)[16], float c, float s) {
#pragma unroll
    for (int i = 0; i < 16; i++) if (!(i & M)) {
        const int j = i | M;
        float xr = ar[i], xi = ai[i], yr = ar[j], yi = ai[j];
        ar[i] = c * xr - s * yr;  ai[i] = c * xi - s * yi;
        ar[j] = s * xr + c * yr;  ai[j] = s * xi + c * yi;
    }
}
template<int M>
__device__ __forceinline__ void g_rx(float (&ar)[16], float (&ai)[16], float c, float s) {
#pragma unroll
    for (int i = 0; i < 16; i++) if (!(i & M)) {
        const int j = i | M;
        float xr = ar[i], xi = ai[i], yr = ar[j], yi = ai[j];
        ar[i] = c * xr + s * yi;   ai[i] = c * xi - s * yr;
        ar[j] = s * xi + c * yr;   ai[j] = -s * xr + c * yi;
    }
}
template<int M>
__device__ __forceinline__ void g_rz(float (&ar)[16], float (&ai)[16], float c, float s) {
#pragma unroll
    for (int i = 0; i < 16; i++) if (!(i & M)) {
        const int j = i | M;
        float xr = ar[i], xi = ai[i], yr = ar[j], yi = ai[j];
        ar[i] = c * xr + s * xi;   ai[i] = c * xi - s * xr;   // * (c - i s)
        ar[j] = c * yr - s * yi;   ai[j] = c * yi + s * yr;   // * (c + i s)
    }
}
template<int MC, int MT>
__device__ __forceinline__ void g_cnot(float (&ar)[16], float (&ai)[16]) {
#pragma unroll
    for (int i = 0; i < 16; i++) if ((i & MC) && !(i & MT)) {
        const int j = i | MT;
        float tr = ar[i]; ar[i] = ar[j]; ar[j] = tr;
        float ti = ai[i]; ai[i] = ai[j]; ai[j] = ti;
    }
}

__global__ __launch_bounds__(NT)
void qcritic_kernel(const float* __restrict__ state,
                    const float* __restrict__ action,
                    const float* __restrict__ W1a, const float* __restrict__ b1a,
                    const float* __restrict__ W2a, const float* __restrict__ b2a,
                    const float* __restrict__ W1b, const float* __restrict__ b1b,
                    const float* __restrict__ W2b, const float* __restrict__ b2b,
                    const float* __restrict__ qwa, const float* __restrict__ qwb,
                    const float* __restrict__ pwa, const float* __restrict__ pba,
                    const float* __restrict__ pwb, const float* __restrict__ pbb,
                    float* __restrict__ out, int Btot)
{
    extern __shared__ float smem[];
    float* xs   = smem + XS_OFF;    // [160][128]
    float* wsm  = smem + WS_OFF;    // [16][132]
    float* qin  = smem + QIN_OFF;   // [128][4]
    float* trgc = smem + TRC_OFF;
    float* trgs = smem + TRS_OFF;

    const int tid  = threadIdx.x;
    const int tx   = tid & 15;      // 16 col-groups
    const int ty   = tid >> 4;      // 16 row-groups
    const int row0 = ty * 8;
    const int col8 = tx * 8;
    const int rowg0 = blockIdx.x * TB;

    // ---- load x tile transposed into smem: xs[k][row] ----
    for (int idx = tid; idx < TB * 40; idx += NT) {
        const int r = idx / 40, k4 = idx % 40;
        float4 v;
        if (k4 < 32) v = ((const float4*)(state  + (size_t)(rowg0 + r) * 128))[k4];
        else         v = ((const float4*)(action + (size_t)(rowg0 + r) * 32))[k4 - 32];
        const int k = k4 * 4;
        xs[(k + 0) * TB + r] = v.x;  xs[(k + 1) * TB + r] = v.y;
        xs[(k + 2) * TB + r] = v.z;  xs[(k + 3) * TB + r] = v.w;
    }

#pragma unroll 1
    for (int br = 0; br < 2; br++) {
        const float* W1 = br ? W1b : W1a;
        const float* b1 = br ? b1b : b1a;
        const float* W2 = br ? W2b : W2a;
        const float* b2 = br ? b2b : b2a;
        const float* qw = br ? qwb : qwa;
        const float  pw = br ? pwb[0] : pwa[0];
        const float  pb = br ? pbb[0] : pba[0];

        __syncthreads();  // xs ready (br0) / previous branch circuit done (br1)
        if (tid < 24) {
            float sv, cv;
            sincosf(0.5f * qw[tid], &sv, &cv);
            trgc[tid] = cv; trgs[tid] = sv;
        }

#pragma unroll 1
        for (int pass = 0; pass < 2; pass++) {
            const int colbase = pass * 128;
            float acc[8][8];
#pragma unroll
            for (int i = 0; i < 8; i++)
#pragma unroll
                for (int j = 0; j < 8; j++) acc[i][j] = 0.f;

#pragma unroll 1
            for (int kc = 0; kc < KDIM; kc += 16) {
                __syncthreads();  // prior wsm reads done
                // load W1 chunk: wsm[kk][col] = W1[colbase+col][kc+kk]
                for (int idx = tid; idx < 512; idx += NT) {
                    const int col = idx >> 2, k4 = idx & 3;
                    float4 v = *(const float4*)(W1 + (size_t)(colbase + col) * KDIM + kc + k4 * 4);
                    const int kk = k4 * 4;
                    wsm[(kk + 0) * 132 + col] = v.x;  wsm[(kk + 1) * 132 + col] = v.y;
                    wsm[(kk + 2) * 132 + col] = v.z;  wsm[(kk + 3) * 132 + col] = v.w;
                }
                __syncthreads();
#pragma unroll
                for (int kk = 0; kk < 16; kk++) {
                    const float4 a0 = *(const float4*)&xs[(kc + kk) * TB + row0];
                    const float4 a1 = *(const float4*)&xs[(kc + kk) * TB + row0 + 4];
                    const float4 w0 = *(const float4*)&wsm[kk * 132 + col8];
                    const float4 w1 = *(const float4*)&wsm[kk * 132 + col8 + 4];
                    const float a[8] = {a0.x, a0.y, a0.z, a0.w, a1.x, a1.y, a1.z, a1.w};
                    const float b[8] = {w0.x, w0.y, w0.z, w0.w, w1.x, w1.y, w1.z, w1.w};
#pragma unroll
                    for (int i = 0; i < 8; i++)
#pragma unroll
                        for (int j = 0; j < 8; j++)
                            acc[i][j] = fmaf(a[i], b[j], acc[i][j]);
                }
            }

            // ---- bias + relu + W2 contraction into per-row partial qin ----
            float part[8][4];
#pragma unroll
            for (int i = 0; i < 8; i++)
#pragma unroll
                for (int j = 0; j < 4; j++) part[i][j] = 0.f;

#pragma unroll
            for (int jj = 0; jj < 8; jj++) {
                const int col = colbase + col8 + jj;
                const float bb  = b1[col];
                const float w20 = W2[col], w21 = W2[256 + col],
                            w22 = W2[512 + col], w23 = W2[768 + col];
#pragma unroll
                for (int i = 0; i < 8; i++) {
                    const float h = fmaxf(acc[i][jj] + bb, 0.f);
                    part[i][0] = fmaf(h, w20, part[i][0]);
                    part[i][1] = fmaf(h, w21, part[i][1]);
                    part[i][2] = fmaf(h, w22, part[i][2]);
                    part[i][3] = fmaf(h, w23, part[i][3]);
                }
            }
            // reduce across 16 tx lanes (stays inside each half-warp)
#pragma unroll
            for (int off = 8; off > 0; off >>= 1)
#pragma unroll
                for (int i = 0; i < 8; i++)
#pragma unroll
                    for (int j = 0; j < 4; j++)
                        part[i][j] += __shfl_xor_sync(0xffffffffu, part[i][j], off);

            if (tx == 0) {
#pragma unroll
                for (int i = 0; i < 8; i++)
#pragma unroll
                    for (int j = 0; j < 4; j++) {
                        if (pass == 0) qin[(row0 + i) * 4 + j]  = part[i][j];
                        else           qin[(row0 + i) * 4 + j] += part[i][j];
                    }
            }
        }

        __syncthreads();  // qin + trig ready

        // ---- 4-qubit statevector circuit, one row per thread ----
        if (tid < TB) {
            float th[4];
#pragma unroll
            for (int j = 0; j < 4; j++) th[j] = qin[tid * 4 + j] + b2[j];

            float ar[16], ai[16];
#pragma unroll
            for (int i = 0; i < 16; i++) { ar[i] = 0.f; ai[i] = 0.f; }
            ar[0] = 1.f;

            // data-encoding RY per qubit (q -> mask 8>>q)
            float s0, c0;
            sincosf(0.5f * th[0], &s0, &c0);  g_ry<8>(ar, ai, c0, s0);
            sincosf(0.5f * th[1], &s0, &c0);  g_ry<4>(ar, ai, c0, s0);
            sincosf(0.5f * th[2], &s0, &c0);  g_ry<2>(ar, ai, c0, s0);
            sincosf(0.5f * th[3], &s0, &c0);  g_ry<1>(ar, ai, c0, s0);

#pragma unroll
            for (int l = 0; l < 2; l++) {
                const int lb = l * 12;
                g_rx<8>(ar, ai, trgc[lb + 0],  trgs[lb + 0]);
                g_ry<8>(ar, ai, trgc[lb + 1],  trgs[lb + 1]);
                g_rz<8>(ar, ai, trgc[lb + 2],  trgs[lb + 2]);
                g_rx<4>(ar, ai, trgc[lb + 3],  trgs[lb + 3]);
                g_ry<4>(ar, ai, trgc[lb + 4],  trgs[lb + 4]);
                g_rz<4>(ar, ai, trgc[lb + 5],  trgs[lb + 5]);
                g_rx<2>(ar, ai, trgc[lb + 6],  trgs[lb + 6]);
                g_ry<2>(ar, ai, trgc[lb + 7],  trgs[lb + 7]);
                g_rz<2>(ar, ai, trgc[lb + 8],  trgs[lb + 8]);
                g_rx<1>(ar, ai, trgc[lb + 9],  trgs[lb + 9]);
                g_ry<1>(ar, ai, trgc[lb + 10], trgs[lb + 10]);
                g_rz<1>(ar, ai, trgc[lb + 11], trgs[lb + 11]);
                g_cnot<8, 4>(ar, ai);   // cnot(0,1)
                g_cnot<4, 2>(ar, ai);   // cnot(1,2)
                g_cnot<2, 1>(ar, ai);   // cnot(2,3)
                g_cnot<1, 8>(ar, ai);   // cnot(3,0)
            }

            float ev = 0.f;
#pragma unroll
            for (int i = 0; i < 16; i++) {
                const float p = ar[i] * ar[i] + ai[i] * ai[i];
                ev += (i & 8) ? -p : p;
            }
            out[(size_t)br * Btot + rowg0 + tid] = fmaf(ev, pw, pb);
        }
    }
}

extern "C" void kernel_launch(void* const* d_in, const int* in_sizes, int n_in,
                              void* d_out, int out_size)
{
    const int Btot = in_sizes[0] / 128;   // state is [B,128]
    const int grid = Btot / TB;
    static bool attr_set = false;
    if (!attr_set) {
        cudaFuncSetAttribute(qcritic_kernel,
                             cudaFuncAttributeMaxDynamicSharedMemorySize,
                             SMEM_FLOATS * sizeof(float));
        attr_set = true;
    }
    qcritic_kernel<<<grid, NT, SMEM_FLOATS * sizeof(float)>>>(
        (const float*)d_in[0],  (const float*)d_in[1],
        (const float*)d_in[2],  (const float*)d_in[3],
        (const float*)d_in[4],  (const float*)d_in[5],
        (const float*)d_in[6],  (const float*)d_in[7],
        (const float*)d_in[8],  (const float*)d_in[9],
        (const float*)d_in[10], (const float*)d_in[11],
        (const float*)d_in[12], (const float*)d_in[13],
        (const float*)d_in[14], (const float*)d_in[15],
        (float*)d_out, Btot);
}

// round 3
// speedup vs baseline: 2.0928x; 2.0928x over previous
#include <cuda_runtime.h>
#include <cuda_bf16.h>
#include <math.h>
#include <stdint.h>

#define NT 256
#define TB 128
#define KDIM 160
#define RS 168           // k-stride (elements) for A/B smem tiles

// smem byte offsets
#define OFF_AHI 0
#define OFF_ALO 43008
#define OFF_BHI 86016
#define OFF_BLO 129024
#define OFF_QIN 172032   // float [2][128][4]
#define OFF_B1  176128   // float [2][256]
#define OFF_W2T 178176   // float [2][256][4]
#define OFF_B2  186368   // float [2][4]
#define OFF_TRC 186400   // float [2][24]
#define OFF_TRS 186592
#define OFF_PP  186784   // pwa,pba,pwb,pbb
#define SMEM_BYTES 186800

// W1 pre-split into bf16 hi/lo, [br][n][RS]
__device__ __align__(16) __nv_bfloat16 g_W1hi[2][256][RS];
__device__ __align__(16) __nv_bfloat16 g_W1lo[2][256][RS];

__device__ __forceinline__ void mma_bf16(float (&d)[4], const uint32_t (&a)[4],
                                         uint32_t b0, uint32_t b1) {
    asm volatile(
        "mma.sync.aligned.m16n8k16.row.col.f32.bf16.bf16.f32 "
        "{%0,%1,%2,%3}, {%4,%5,%6,%7}, {%8,%9}, {%0,%1,%2,%3};"
        : "+f"(d[0]), "+f"(d[1]), "+f"(d[2]), "+f"(d[3])
        : "r"(a[0]), "r"(a[1]), "r"(a[2]), "r"(a[3]), "r"(b0), "r"(b1));
}

// ---------------- quantum gates on 16-amplitude register state ----------------
template<int M>
__device__ __forceinline__ void g_ry(float (&ar)[16], float (&ai)[16], float c, float s) {
#pragma unroll
    for (int i = 0; i < 16; i++) if (!(i & M)) {
        const int j = i | M;
        float xr = ar[i], xi = ai[i], yr = ar[j], yi = ai[j];
        ar[i] = c * xr - s * yr;  ai[i] = c * xi - s * yi;
        ar[j] = s * xr + c * yr;  ai[j] = s * xi + c * yi;
    }
}
template<int M>
__device__ __forceinline__ void g_rx(float (&ar)[16], float (&ai)[16], float c, float s) {
#pragma unroll
    for (int i = 0; i < 16; i++) if (!(i & M)) {
        const int j = i | M;
        float xr = ar[i], xi = ai[i], yr = ar[j], yi = ai[j];
        ar[i] = c * xr + s * yi;   ai[i] = c * xi - s * yr;
        ar[j] = s * xi + c * yr;   ai[j] = -s * xr + c * yi;
    }
}
template<int M>
__device__ __forceinline__ void g_rz(float (&ar)[16], float (&ai)[16], float c, float s) {
#pragma unroll
    for (int i = 0; i < 16; i++) if (!(i & M)) {
        const int j = i | M;
        float xr = ar[i], xi = ai[i], yr = ar[j], yi = ai[j];
        ar[i] = c * xr + s * xi;   ai[i] = c * xi - s * xr;
        ar[j] = c * yr - s * yi;   ai[j] = c * yi + s * yr;
    }
}
template<int MC, int MT>
__device__ __forceinline__ void g_cnot(float (&ar)[16], float (&ai)[16]) {
#pragma unroll
    for (int i = 0; i < 16; i++) if ((i & MC) && !(i & MT)) {
        const int j = i | MT;
        float tr = ar[i]; ar[i] = ar[j]; ar[j] = tr;
        float ti = ai[i]; ai[i] = ai[j]; ai[j] = ti;
    }
}

// ---------------- prep: W1 -> bf16 hi/lo ----------------
__global__ void qprep(const float* __restrict__ W1a, const float* __restrict__ W1b) {
    const int t = blockIdx.x * 256 + threadIdx.x;    // 0..20479
    const int br = t / 10240;
    const int rem = t % 10240;
    const int n = rem / 40, k4 = rem % 40;
    const float4 v = *(const float4*)((br ? W1b : W1a) + (size_t)n * KDIM + k4 * 4);
    const float vals[4] = {v.x, v.y, v.z, v.w};
#pragma unroll
    for (int j = 0; j < 4; j++) {
        const __nv_bfloat16 h = __float2bfloat16(vals[j]);
        g_W1hi[br][n][k4 * 4 + j] = h;
        g_W1lo[br][n][k4 * 4 + j] = __float2bfloat16(vals[j] - __bfloat162float(h));
    }
}

// ---------------- main kernel ----------------
__global__ __launch_bounds__(NT, 1)
void qmain(const float* __restrict__ state, const float* __restrict__ action,
           const float* __restrict__ b1a, const float* __restrict__ W2a, const float* __restrict__ b2a,
           const float* __restrict__ b1b, const float* __restrict__ W2b, const float* __restrict__ b2b,
           const float* __restrict__ qwa, const float* __restrict__ qwb,
           const float* __restrict__ pwa, const float* __restrict__ pba,
           const float* __restrict__ pwb, const float* __restrict__ pbb,
           float* __restrict__ out, int Btot)
{
    extern __shared__ __align__(16) unsigned char smp[];
    float* smf = (float*)smp;
    __nv_bfloat16* Ahi = (__nv_bfloat16*)(smp + OFF_AHI);
    __nv_bfloat16* Alo = (__nv_bfloat16*)(smp + OFF_ALO);
    __nv_bfloat16* Bhi = (__nv_bfloat16*)(smp + OFF_BHI);
    __nv_bfloat16* Blo = (__nv_bfloat16*)(smp + OFF_BLO);
    float* qin = smf + OFF_QIN / 4;

    const int tid = threadIdx.x;
    const int lane = tid & 31, w = tid >> 5;
    const int gid = lane >> 2, tig = lane & 3;
    const int wm = w & 3, wn = w >> 2;
    const int m0 = wm * 32, n0 = wn * 64;
    const int rowg0 = blockIdx.x * TB;

    // ---- params into smem ----
    for (int i = tid; i < 512; i += NT)
        smf[OFF_B1 / 4 + i] = ((i >> 8) ? b1b : b1a)[i & 255];
    for (int i = tid; i < 2048; i += NT) {
        const int br = i >> 10, rem = i & 1023, n = rem >> 2, q = rem & 3;
        smf[OFF_W2T / 4 + i] = (br ? W2b : W2a)[q * 256 + n];
    }
    if (tid < 8)  smf[OFF_B2 / 4 + tid] = ((tid >> 2) ? b2b : b2a)[tid & 3];
    if (tid < 48) {
        const int br = tid / 24, g = tid % 24;
        float sv, cv;
        sincosf(0.5f * (br ? qwb : qwa)[g], &sv, &cv);
        smf[OFF_TRC / 4 + tid] = cv;  smf[OFF_TRS / 4 + tid] = sv;
    }
    if (tid < 4)
        smf[OFF_PP / 4 + tid] = (tid == 0) ? pwa[0] : (tid == 1) ? pba[0]
                               : (tid == 2) ? pwb[0] : pbb[0];
    for (int i = tid; i < 1024; i += NT) qin[i] = 0.f;

    // ---- x -> A hi/lo smem [row][k], stride RS ----
    {
        const int r = tid >> 1, hf = tid & 1;
        const float* srow = state  + (size_t)(rowg0 + r) * 128;
        const float* arow = action + (size_t)(rowg0 + r) * 32;
#pragma unroll 5
        for (int i = 0; i < 20; i++) {
            const int k = hf * 80 + i * 4;
            const float4 v = (k < 128) ? *(const float4*)(srow + k)
                                       : *(const float4*)(arow + (k - 128));
            const float vals[4] = {v.x, v.y, v.z, v.w};
#pragma unroll
            for (int p = 0; p < 2; p++) {
                const float a = vals[p * 2], b = vals[p * 2 + 1];
                const __nv_bfloat16 ha = __float2bfloat16(a), hb = __float2bfloat16(b);
                *(__nv_bfloat162*)(Ahi + r * RS + k + p * 2) = __halves2bfloat162(ha, hb);
                *(__nv_bfloat162*)(Alo + r * RS + k + p * 2) =
                    __halves2bfloat162(__float2bfloat16(a - __bfloat162float(ha)),
                                       __float2bfloat16(b - __bfloat162float(hb)));
            }
        }
    }
    __syncthreads();

    // ---- 4 passes: (branch, n-chunk) ----
#pragma unroll 1
    for (int pass = 0; pass < 4; pass++) {
        const int br = pass >> 1, chunk = pass & 1;
        const int nbase = chunk * 128;

        if (pass) __syncthreads();   // all warps done reading previous B
        {
            const uint4* srcH = (const uint4*)&g_W1hi[br][nbase][0];
            const uint4* srcL = (const uint4*)&g_W1lo[br][nbase][0];
            uint4* dstH = (uint4*)Bhi;
            uint4* dstL = (uint4*)Blo;
#pragma unroll 1
            for (int i = tid; i < 2688; i += NT) { dstH[i] = srcH[i]; dstL[i] = srcL[i]; }
        }
        __syncthreads();

        float acc[2][8][4];
#pragma unroll
        for (int mf = 0; mf < 2; mf++)
#pragma unroll
            for (int nf = 0; nf < 8; nf++)
#pragma unroll
                for (int c = 0; c < 4; c++) acc[mf][nf][c] = 0.f;

#pragma unroll 1
        for (int ks = 0; ks < 10; ks++) {
            const int k0 = ks * 16;
            uint32_t ah[2][4], al[2][4];
#pragma unroll
            for (int mf = 0; mf < 2; mf++) {
                const int base = (m0 + mf * 16 + gid) * RS + k0 + 2 * tig;
                ah[mf][0] = *(const uint32_t*)(Ahi + base);
                ah[mf][1] = *(const uint32_t*)(Ahi + base + 8 * RS);
                ah[mf][2] = *(const uint32_t*)(Ahi + base + 8);
                ah[mf][3] = *(const uint32_t*)(Ahi + base + 8 * RS + 8);
                al[mf][0] = *(const uint32_t*)(Alo + base);
                al[mf][1] = *(const uint32_t*)(Alo + base + 8 * RS);
                al[mf][2] = *(const uint32_t*)(Alo + base + 8);
                al[mf][3] = *(const uint32_t*)(Alo + base + 8 * RS + 8);
            }
#pragma unroll
            for (int nf = 0; nf < 8; nf++) {
                const int bbase = (n0 + nf * 8 + gid) * RS + k0 + 2 * tig;
                const uint32_t bh0 = *(const uint32_t*)(Bhi + bbase);
                const uint32_t bh1 = *(const uint32_t*)(Bhi + bbase + 8);
                const uint32_t bl0 = *(const uint32_t*)(Blo + bbase);
                const uint32_t bl1 = *(const uint32_t*)(Blo + bbase + 8);
#pragma unroll
                for (int mf = 0; mf < 2; mf++) {
                    mma_bf16(acc[mf][nf], ah[mf], bh0, bh1);
                    mma_bf16(acc[mf][nf], al[mf], bh0, bh1);
                    mma_bf16(acc[mf][nf], ah[mf], bl0, bl1);
                }
            }
        }

        // ---- epilogue: bias + relu + W2 contraction -> qin ----
        const float* b1s = smf + OFF_B1 / 4 + br * 256;
        const float* w2t = smf + OFF_W2T / 4 + br * 1024;
#pragma unroll
        for (int mf = 0; mf < 2; mf++) {
            const int r0 = m0 + mf * 16 + gid;
            float p0[4] = {0.f, 0.f, 0.f, 0.f}, p1[4] = {0.f, 0.f, 0.f, 0.f};
#pragma unroll
            for (int nf = 0; nf < 8; nf++)
#pragma unroll
                for (int c = 0; c < 2; c++) {
                    const int gcol = nbase + n0 + nf * 8 + 2 * tig + c;
                    const float bb = b1s[gcol];
                    const float h0 = fmaxf(acc[mf][nf][c] + bb, 0.f);
                    const float h1 = fmaxf(acc[mf][nf][2 + c] + bb, 0.f);
                    const float4 wv = *(const float4*)(w2t + gcol * 4);
                    p0[0] = fmaf(h0, wv.x, p0[0]);  p0[1] = fmaf(h0, wv.y, p0[1]);
                    p0[2] = fmaf(h0, wv.z, p0[2]);  p0[3] = fmaf(h0, wv.w, p0[3]);
                    p1[0] = fmaf(h1, wv.x, p1[0]);  p1[1] = fmaf(h1, wv.y, p1[1]);
                    p1[2] = fmaf(h1, wv.z, p1[2]);  p1[3] = fmaf(h1, wv.w, p1[3]);
                }
#pragma unroll
            for (int off = 1; off <= 2; off <<= 1)
#pragma unroll
                for (int j = 0; j < 4; j++) {
                    p0[j] += __shfl_xor_sync(0xffffffffu, p0[j], off);
                    p1[j] += __shfl_xor_sync(0xffffffffu, p1[j], off);
                }
            if (tig == 0) {
                float* q0 = qin + ((br << 7) + r0) * 4;
                float* q1 = qin + ((br << 7) + r0 + 8) * 4;
#pragma unroll
                for (int j = 0; j < 4; j++) {
                    atomicAdd(q0 + j, p0[j]);
                    atomicAdd(q1 + j, p1[j]);
                }
            }
        }
    }
    __syncthreads();

    // ---- quantum circuit: 1 row/thread, 128 rows x 2 branches ----
    {
        const int br = tid >> 7, row = tid & 127;
        const float* b2s = smf + OFF_B2 / 4 + br * 4;
        const float* trc = smf + OFF_TRC / 4 + br * 24;
        const float* trs = smf + OFF_TRS / 4 + br * 24;
        const float pw = smf[OFF_PP / 4 + br * 2];
        const float pb = smf[OFF_PP / 4 + br * 2 + 1];
        const float* qv = qin + ((br << 7) + row) * 4;
        const float th[4] = {qv[0] + b2s[0], qv[1] + b2s[1], qv[2] + b2s[2], qv[3] + b2s[3]};

        float ar[16], ai[16];
#pragma unroll
        for (int i = 0; i < 16; i++) { ar[i] = 0.f; ai[i] = 0.f; }
        ar[0] = 1.f;

        float s0, c0;
        sincosf(0.5f * th[0], &s0, &c0);  g_ry<8>(ar, ai, c0, s0);
        sincosf(0.5f * th[1], &s0, &c0);  g_ry<4>(ar, ai, c0, s0);
        sincosf(0.5f * th[2], &s0, &c0);  g_ry<2>(ar, ai, c0, s0);
        sincosf(0.5f * th[3], &s0, &c0);  g_ry<1>(ar, ai, c0, s0);

#pragma unroll
        for (int l = 0; l < 2; l++) {
            const int lb = l * 12;
            g_rx<8>(ar, ai, trc[lb + 0],  trs[lb + 0]);
            g_ry<8>(ar, ai, trc[lb + 1],  trs[lb + 1]);
            g_rz<8>(ar, ai, trc[lb + 2],  trs[lb + 2]);
            g_rx<4>(ar, ai, trc[lb + 3],  trs[lb + 3]);
            g_ry<4>(ar, ai, trc[lb + 4],  trs[lb + 4]);
            g_rz<4>(ar, ai, trc[lb + 5],  trs[lb + 5]);
            g_rx<2>(ar, ai, trc[lb + 6],  trs[lb + 6]);
            g_ry<2>(ar, ai, trc[lb + 7],  trs[lb + 7]);
            g_rz<2>(ar, ai, trc[lb + 8],  trs[lb + 8]);
            g_rx<1>(ar, ai, trc[lb + 9],  trs[lb + 9]);
            g_ry<1>(ar, ai, trc[lb + 10], trs[lb + 10]);
            g_rz<1>(ar, ai, trc[lb + 11], trs[lb + 11]);
            g_cnot<8, 4>(ar, ai);
            g_cnot<4, 2>(ar, ai);
            g_cnot<2, 1>(ar, ai);
            g_cnot<1, 8>(ar, ai);
        }

        float ev = 0.f;
#pragma unroll
        for (int i = 0; i < 16; i++) {
            const float p = ar[i] * ar[i] + ai[i] * ai[i];
            ev += (i & 8) ? -p : p;
        }
        out[(size_t)br * Btot + rowg0 + row] = fmaf(ev, pw, pb);
    }
}

extern "C" void kernel_launch(void* const* d_in, const int* in_sizes, int n_in,
                              void* d_out, int out_size)
{
    const int Btot = in_sizes[0] / 128;
    static bool attr_set = false;
    if (!attr_set) {
        cudaFuncSetAttribute(qmain, cudaFuncAttributeMaxDynamicSharedMemorySize, SMEM_BYTES);
        attr_set = true;
    }
    qprep<<<80, 256>>>((const float*)d_in[2], (const float*)d_in[6]);
    qmain<<<Btot / TB, NT, SMEM_BYTES>>>(
        (const float*)d_in[0],  (const float*)d_in[1],
        (const float*)d_in[3],  (const float*)d_in[4],  (const float*)d_in[5],
        (const float*)d_in[7],  (const float*)d_in[8],  (const float*)d_in[9],
        (const float*)d_in[10], (const float*)d_in[11],
        (const float*)d_in[12], (const float*)d_in[13],
        (const float*)d_in[14], (const float*)d_in[15],
        (float*)d_out, Btot);
}

// round 4
// speedup vs baseline: 2.5106x; 1.1997x over previous
#include <cuda_runtime.h>
#include <cuda_bf16.h>
#include <math.h>
#include <stdint.h>

#define NT 256
#define TB 128
#define KDIM 160
#define RS 168           // k-stride (elements) for A/B smem tiles

// smem byte offsets
#define OFF_AHI 0
#define OFF_ALO 43008
#define OFF_B   86016    // [buf][hi/lo][64][RS] bf16 : 4 x 21504
#define OFF_QIN 172032   // float [2][128][4]
#define OFF_B1  176128   // float [2][256]
#define OFF_W2T 178176   // float [2][256][4]
#define OFF_B2  186368
#define OFF_TRC 186400
#define OFF_TRS 186592
#define OFF_PP  186784
#define SMEM_BYTES 186800

#define BCH 21504        // bytes per (buf,hi/lo) B chunk

// W1 pre-split into bf16 hi/lo, [br][n][RS]
__device__ __align__(16) __nv_bfloat16 g_W1hi[2][256][RS];
__device__ __align__(16) __nv_bfloat16 g_W1lo[2][256][RS];

__device__ __forceinline__ uint32_t smem_u32(const void* p) {
    uint32_t a;
    asm("{ .reg .u64 t; cvta.to.shared.u64 t, %1; cvt.u32.u64 %0, t; }" : "=r"(a) : "l"(p));
    return a;
}
__device__ __forceinline__ void mma_bf16(float (&d)[4], const uint32_t (&a)[4],
                                         uint32_t b0, uint32_t b1) {
    asm volatile(
        "mma.sync.aligned.m16n8k16.row.col.f32.bf16.bf16.f32 "
        "{%0,%1,%2,%3}, {%4,%5,%6,%7}, {%8,%9}, {%0,%1,%2,%3};"
        : "+f"(d[0]), "+f"(d[1]), "+f"(d[2]), "+f"(d[3])
        : "r"(a[0]), "r"(a[1]), "r"(a[2]), "r"(a[3]), "r"(b0), "r"(b1));
}
__device__ __forceinline__ void ldsm4(uint32_t (&r)[4], uint32_t addr) {
    asm volatile("ldmatrix.sync.aligned.m8n8.x4.shared.b16 {%0,%1,%2,%3}, [%4];"
        : "=r"(r[0]), "=r"(r[1]), "=r"(r[2]), "=r"(r[3]) : "r"(addr));
}
#define CPA16(dst, src) asm volatile("cp.async.cg.shared.global [%0], [%1], 16;" :: "r"(dst), "l"(src))
#define CPA_COMMIT()    asm volatile("cp.async.commit_group;")
#define CPA_WAIT1()     asm volatile("cp.async.wait_group 1;")
#define CPA_WAIT0()     asm volatile("cp.async.wait_group 0;")

// ---------------- quantum gates on 16-amplitude register state ----------------
template<int M>
__device__ __forceinline__ void g_ry(float (&ar)[16], float (&ai)[16], float c, float s) {
#pragma unroll
    for (int i = 0; i < 16; i++) if (!(i & M)) {
        const int j = i | M;
        float xr = ar[i], xi = ai[i], yr = ar[j], yi = ai[j];
        ar[i] = c * xr - s * yr;  ai[i] = c * xi - s * yi;
        ar[j] = s * xr + c * yr;  ai[j] = s * xi + c * yi;
    }
}
template<int M>
__device__ __forceinline__ void g_rx(float (&ar)[16], float (&ai)[16], float c, float s) {
#pragma unroll
    for (int i = 0; i < 16; i++) if (!(i & M)) {
        const int j = i | M;
        float xr = ar[i], xi = ai[i], yr = ar[j], yi = ai[j];
        ar[i] = c * xr + s * yi;   ai[i] = c * xi - s * yr;
        ar[j] = s * xi + c * yr;   ai[j] = -s * xr + c * yi;
    }
}
template<int M>
__device__ __forceinline__ void g_rz(float (&ar)[16], float (&ai)[16], float c, float s) {
#pragma unroll
    for (int i = 0; i < 16; i++) if (!(i & M)) {
        const int j = i | M;
        float xr = ar[i], xi = ai[i], yr = ar[j], yi = ai[j];
        ar[i] = c * xr + s * xi;   ai[i] = c * xi - s * xr;
        ar[j] = c * yr - s * yi;   ai[j] = c * yi + s * yr;
    }
}
template<int MC, int MT>
__device__ __forceinline__ void g_cnot(float (&ar)[16], float (&ai)[16]) {
#pragma unroll
    for (int i = 0; i < 16; i++) if ((i & MC) && !(i & MT)) {
        const int j = i | MT;
        float tr = ar[i]; ar[i] = ar[j]; ar[j] = tr;
        float ti = ai[i]; ai[i] = ai[j]; ai[j] = ti;
    }
}

// ---------------- prep: W1 -> bf16 hi/lo ----------------
__global__ void qprep(const float* __restrict__ W1a, const float* __restrict__ W1b) {
    const int t = blockIdx.x * 256 + threadIdx.x;    // 0..20479
    const int br = t / 10240;
    const int rem = t % 10240;
    const int n = rem / 40, k4 = rem % 40;
    const float4 v = *(const float4*)((br ? W1b : W1a) + (size_t)n * KDIM + k4 * 4);
    const float vals[4] = {v.x, v.y, v.z, v.w};
#pragma unroll
    for (int j = 0; j < 4; j++) {
        const __nv_bfloat16 h = __float2bfloat16(vals[j]);
        g_W1hi[br][n][k4 * 4 + j] = h;
        g_W1lo[br][n][k4 * 4 + j] = __float2bfloat16(vals[j] - __bfloat162float(h));
    }
}

// ---------------- main kernel ----------------
__global__ __launch_bounds__(NT, 1)
void qmain(const float* __restrict__ state, const float* __restrict__ action,
           const float* __restrict__ b1a, const float* __restrict__ W2a, const float* __restrict__ b2a,
           const float* __restrict__ b1b, const float* __restrict__ W2b, const float* __restrict__ b2b,
           const float* __restrict__ qwa, const float* __restrict__ qwb,
           const float* __restrict__ pwa, const float* __restrict__ pba,
           const float* __restrict__ pwb, const float* __restrict__ pbb,
           float* __restrict__ out, int Btot)
{
    extern __shared__ __align__(16) unsigned char smp[];
    float* smf = (float*)smp;
    __nv_bfloat16* Ahi = (__nv_bfloat16*)(smp + OFF_AHI);
    __nv_bfloat16* Alo = (__nv_bfloat16*)(smp + OFF_ALO);
    float* qin = smf + OFF_QIN / 4;
    const uint32_t smb = smem_u32(smp);

    const int tid = threadIdx.x;
    const int lane = tid & 31, w = tid >> 5;
    const int gid = lane >> 2, tig = lane & 3;
    const int wm = w & 3, wn = w >> 2;
    const int m0 = wm * 32, n0 = wn * 32;
    const int rowg0 = blockIdx.x * TB;

    // ---- kick off B loads for pass 0 (buf 0) ----
    {
        const char* srcH = (const char*)&g_W1hi[0][0][0];
        const char* srcL = (const char*)&g_W1lo[0][0][0];
        for (int i = tid; i < BCH / 16; i += NT) {
            CPA16(smb + OFF_B + i * 16, srcH + i * 16);
            CPA16(smb + OFF_B + BCH + i * 16, srcL + i * 16);
        }
        CPA_COMMIT();
    }

    // ---- params into smem ----
    for (int i = tid; i < 512; i += NT)
        smf[OFF_B1 / 4 + i] = ((i >> 8) ? b1b : b1a)[i & 255];
    for (int i = tid; i < 2048; i += NT) {
        const int br = i >> 10, rem = i & 1023, n = rem >> 2, q = rem & 3;
        smf[OFF_W2T / 4 + i] = (br ? W2b : W2a)[q * 256 + n];
    }
    if (tid < 8)  smf[OFF_B2 / 4 + tid] = ((tid >> 2) ? b2b : b2a)[tid & 3];
    if (tid < 48) {
        const int br = tid / 24, g = tid % 24;
        float sv, cv;
        sincosf(0.5f * (br ? qwb : qwa)[g], &sv, &cv);
        smf[OFF_TRC / 4 + tid] = cv;  smf[OFF_TRS / 4 + tid] = sv;
    }
    if (tid < 4)
        smf[OFF_PP / 4 + tid] = (tid == 0) ? pwa[0] : (tid == 1) ? pba[0]
                               : (tid == 2) ? pwb[0] : pbb[0];
    for (int i = tid; i < 1024; i += NT) qin[i] = 0.f;

    // ---- x -> A hi/lo smem [row][k], stride RS ----
    {
        const int r = tid >> 1, hf = tid & 1;
        const float* srow = state  + (size_t)(rowg0 + r) * 128;
        const float* arow = action + (size_t)(rowg0 + r) * 32;
#pragma unroll 5
        for (int i = 0; i < 20; i++) {
            const int k = hf * 80 + i * 4;
            const float4 v = (k < 128) ? *(const float4*)(srow + k)
                                       : *(const float4*)(arow + (k - 128));
            const float vals[4] = {v.x, v.y, v.z, v.w};
#pragma unroll
            for (int p = 0; p < 2; p++) {
                const float a = vals[p * 2], b = vals[p * 2 + 1];
                const __nv_bfloat16 ha = __float2bfloat16(a), hb = __float2bfloat16(b);
                *(__nv_bfloat162*)(Ahi + r * RS + k + p * 2) = __halves2bfloat162(ha, hb);
                *(__nv_bfloat162*)(Alo + r * RS + k + p * 2) =
                    __halves2bfloat162(__float2bfloat16(a - __bfloat162float(ha)),
                                       __float2bfloat16(b - __bfloat162float(hb)));
            }
        }
    }

    // ---- ldmatrix address components (element offsets) ----
    // A: row = m0 + mf*16 + (lane&15), col = 8*(lane>>4)
    const uint32_t aoff0 = (uint32_t)((m0 + (lane & 15)) * RS + 8 * (lane >> 4));
    const uint32_t aoff1 = aoff0 + 16u * RS;
    // B: row = n0loc + p*16 + 8*(lane>>4) + (lane&7), col = 8*((lane>>3)&1)
    const uint32_t boff0 = (uint32_t)((n0 + 8 * (lane >> 4) + (lane & 7)) * RS
                                      + 8 * ((lane >> 3) & 1));
    const uint32_t boff1 = boff0 + 16u * RS;

    // per-row W2 partials, accumulated across the 4 passes of each branch
    float p0[4] = {0.f, 0.f, 0.f, 0.f}, p1[4] = {0.f, 0.f, 0.f, 0.f};

#pragma unroll 1
    for (int pass = 0; pass < 8; pass++) {
        const int br = pass >> 2, chunk = pass & 3;
        const int nbase = chunk * 64;
        const int buf = pass & 1;

        // issue B loads for next pass into the other buffer
        if (pass < 7) {
            const int pN = pass + 1;
            const char* srcH = (const char*)&g_W1hi[pN >> 2][(pN & 3) * 64][0];
            const char* srcL = (const char*)&g_W1lo[pN >> 2][(pN & 3) * 64][0];
            const uint32_t dst = smb + OFF_B + (uint32_t)(pN & 1) * (2 * BCH);
            for (int i = tid; i < BCH / 16; i += NT) {
                CPA16(dst + i * 16, srcH + i * 16);
                CPA16(dst + BCH + i * 16, srcL + i * 16);
            }
            CPA_COMMIT();
            CPA_WAIT1();
        } else {
            CPA_WAIT0();
        }
        __syncthreads();   // current buf ready for all warps

        const uint32_t bhB = smb + OFF_B + (uint32_t)buf * (2 * BCH);
        const uint32_t blB = bhB + BCH;

        float acc[2][4][4];
#pragma unroll
        for (int mf = 0; mf < 2; mf++)
#pragma unroll
            for (int nf = 0; nf < 4; nf++)
#pragma unroll
                for (int c = 0; c < 4; c++) acc[mf][nf][c] = 0.f;

#pragma unroll 1
        for (int ks = 0; ks < 10; ks++) {
            const uint32_t k0 = (uint32_t)(ks * 16);
            uint32_t ah[2][4], al[2][4], bh[2][4], bl[2][4];
            ldsm4(ah[0], smb + OFF_AHI + (aoff0 + k0) * 2);
            ldsm4(ah[1], smb + OFF_AHI + (aoff1 + k0) * 2);
            ldsm4(al[0], smb + OFF_ALO + (aoff0 + k0) * 2);
            ldsm4(al[1], smb + OFF_ALO + (aoff1 + k0) * 2);
            ldsm4(bh[0], bhB + (boff0 + k0) * 2);
            ldsm4(bh[1], bhB + (boff1 + k0) * 2);
            ldsm4(bl[0], blB + (boff0 + k0) * 2);
            ldsm4(bl[1], blB + (boff1 + k0) * 2);
#pragma unroll
            for (int p = 0; p < 2; p++)
#pragma unroll
                for (int q = 0; q < 2; q++) {
                    const int nf = p * 2 + q;
#pragma unroll
                    for (int mf = 0; mf < 2; mf++) {
                        mma_bf16(acc[mf][nf], ah[mf], bh[p][q * 2], bh[p][q * 2 + 1]);
                        mma_bf16(acc[mf][nf], al[mf], bh[p][q * 2], bh[p][q * 2 + 1]);
                        mma_bf16(acc[mf][nf], ah[mf], bl[p][q * 2], bl[p][q * 2 + 1]);
                    }
                }
        }

        // ---- bias + relu + W2 contraction into register partials ----
        const float* b1s = smf + OFF_B1 / 4 + br * 256;
        const float* w2t = smf + OFF_W2T / 4 + br * 1024;
#pragma unroll
        for (int mf = 0; mf < 2; mf++) {
            float* pp = mf ? p1 : p0;
#pragma unroll
            for (int nf = 0; nf < 4; nf++)
#pragma unroll
                for (int c = 0; c < 2; c++) {
                    const int gcol = nbase + n0 + nf * 8 + 2 * tig + c;
                    const float bb = b1s[gcol];
                    const float h0 = fmaxf(acc[mf][nf][c] + bb, 0.f);
                    const float h1 = fmaxf(acc[mf][nf][2 + c] + bb, 0.f);
                    const float4 wv = *(const float4*)(w2t + gcol * 4);
                    // rows r0 = m0+mf*16+gid (h0) and r0+8 (h1) share pp slots:
                    // pp[0..3] for h0-row, reuse via second set below
                    pp[0] = fmaf(h0, wv.x, pp[0]);  pp[1] = fmaf(h0, wv.y, pp[1]);
                    pp[2] = fmaf(h0, wv.z, pp[2]);  pp[3] = fmaf(h0, wv.w, pp[3]);
                    // h1 handled in second accumulator set
                    acc[mf][nf][2 + c] = h1;   // stash post-relu for below
                }
        }
        // second-row accumulation (r0+8) into dedicated partials kept in acc-free regs
        // reuse: we fold h1 contributions immediately into shared qin at branch end,
        // so accumulate into registers here:
        {
            static_assert(true, "");
        }
#pragma unroll
        for (int mf = 0; mf < 2; mf++) {
            float s[4] = {0.f, 0.f, 0.f, 0.f};
#pragma unroll
            for (int nf = 0; nf < 4; nf++)
#pragma unroll
                for (int c = 0; c < 2; c++) {
                    const int gcol = nbase + n0 + nf * 8 + 2 * tig + c;
                    const float h1 = acc[mf][nf][2 + c];
                    const float4 wv = *(const float4*)(w2t + gcol * 4);
                    s[0] = fmaf(h1, wv.x, s[0]);  s[1] = fmaf(h1, wv.y, s[1]);
                    s[2] = fmaf(h1, wv.z, s[2]);  s[3] = fmaf(h1, wv.w, s[3]);
                }
            // fold row+8 partials via shuffle by 4 trick: keep in qin directly
            // reduce over tig lanes now (cheap: 2 shuffles per value)
#pragma unroll
            for (int off = 1; off <= 2; off <<= 1)
#pragma unroll
                for (int j = 0; j < 4; j++)
                    s[j] += __shfl_xor_sync(0xffffffffu, s[j], off);
            if (tig == 0) {
                float* qdst = qin + ((br << 7) + m0 + mf * 16 + gid + 8) * 4;
#pragma unroll
                for (int j = 0; j < 4; j++) atomicAdd(qdst + j, s[j]);
            }
        }

        // flush p0/p1 at branch boundary
        if (chunk == 3) {
#pragma unroll
            for (int off = 1; off <= 2; off <<= 1)
#pragma unroll
                for (int j = 0; j < 4; j++) {
                    p0[j] += __shfl_xor_sync(0xffffffffu, p0[j], off);
                    p1[j] += __shfl_xor_sync(0xffffffffu, p1[j], off);
                }
            if (tig == 0) {
                float* q0 = qin + ((br << 7) + m0 + gid) * 4;
                float* q1 = qin + ((br << 7) + m0 + 16 + gid) * 4;
#pragma unroll
                for (int j = 0; j < 4; j++) {
                    atomicAdd(q0 + j, p0[j]);
                    atomicAdd(q1 + j, p1[j]);
                }
            }
#pragma unroll
            for (int j = 0; j < 4; j++) { p0[j] = 0.f; p1[j] = 0.f; }
        }

        __syncthreads();   // all reads of buf done before it is overwritten
    }
    __syncthreads();

    // ---- quantum circuit: 1 row/thread, 128 rows x 2 branches ----
    {
        const int br = tid >> 7, row = tid & 127;
        const float* b2s = smf + OFF_B2 / 4 + br * 4;
        const float* trc = smf + OFF_TRC / 4 + br * 24;
        const float* trs = smf + OFF_TRS / 4 + br * 24;
        const float pw = smf[OFF_PP / 4 + br * 2];
        const float pb = smf[OFF_PP / 4 + br * 2 + 1];
        const float* qv = qin + ((br << 7) + row) * 4;
        const float th[4] = {qv[0] + b2s[0], qv[1] + b2s[1], qv[2] + b2s[2], qv[3] + b2s[3]};

        float ar[16], ai[16];
#pragma unroll
        for (int i = 0; i < 16; i++) { ar[i] = 0.f; ai[i] = 0.f; }
        ar[0] = 1.f;

        float s0, c0;
        sincosf(0.5f * th[0], &s0, &c0);  g_ry<8>(ar, ai, c0, s0);
        sincosf(0.5f * th[1], &s0, &c0);  g_ry<4>(ar, ai, c0, s0);
        sincosf(0.5f * th[2], &s0, &c0);  g_ry<2>(ar, ai, c0, s0);
        sincosf(0.5f * th[3], &s0, &c0);  g_ry<1>(ar, ai, c0, s0);

#pragma unroll
        for (int l = 0; l < 2; l++) {
            const int lb = l * 12;
            g_rx<8>(ar, ai, trc[lb + 0],  trs[lb + 0]);
            g_ry<8>(ar, ai, trc[lb + 1],  trs[lb + 1]);
            g_rz<8>(ar, ai, trc[lb + 2],  trs[lb + 2]);
            g_rx<4>(ar, ai, trc[lb + 3],  trs[lb + 3]);
            g_ry<4>(ar, ai, trc[lb + 4],  trs[lb + 4]);
            g_rz<4>(ar, ai, trc[lb + 5],  trs[lb + 5]);
            g_rx<2>(ar, ai, trc[lb + 6],  trs[lb + 6]);
            g_ry<2>(ar, ai, trc[lb + 7],  trs[lb + 7]);
            g_rz<2>(ar, ai, trc[lb + 8],  trs[lb + 8]);
            g_rx<1>(ar, ai, trc[lb + 9],  trs[lb + 9]);
            g_ry<1>(ar, ai, trc[lb + 10], trs[lb + 10]);
            g_rz<1>(ar, ai, trc[lb + 11], trs[lb + 11]);
            g_cnot<8, 4>(ar, ai);
            g_cnot<4, 2>(ar, ai);
            g_cnot<2, 1>(ar, ai);
            g_cnot<1, 8>(ar, ai);
        }

        float ev = 0.f;
#pragma unroll
        for (int i = 0; i < 16; i++) {
            const float p = ar[i] * ar[i] + ai[i] * ai[i];
            ev += (i & 8) ? -p : p;
        }
        out[(size_t)br * Btot + rowg0 + row] = fmaf(ev, pw, pb);
    }
}

extern "C" void kernel_launch(void* const* d_in, const int* in_sizes, int n_in,
                              void* d_out, int out_size)
{
    const int Btot = in_sizes[0] / 128;
    static bool attr_set = false;
    if (!attr_set) {
        cudaFuncSetAttribute(qmain, cudaFuncAttributeMaxDynamicSharedMemorySize, SMEM_BYTES);
        attr_set = true;
    }
    qprep<<<80, 256>>>((const float*)d_in[2], (const float*)d_in[6]);
    qmain<<<Btot / TB, NT, SMEM_BYTES>>>(
        (const float*)d_in[0],  (const float*)d_in[1],
        (const float*)d_in[3],  (const float*)d_in[4],  (const float*)d_in[5],
        (const float*)d_in[7],  (const float*)d_in[8],  (const float*)d_in[9],
        (const float*)d_in[10], (const float*)d_in[11],
        (const float*)d_in[12], (const float*)d_in[13],
        (const float*)d_in[14], (const float*)d_in[15],
        (float*)d_out, Btot);
}

// round 5
// speedup vs baseline: 2.5439x; 1.0132x over previous
#include <cuda_runtime.h>
#include <cuda_bf16.h>
#include <math.h>
#include <stdint.h>

#define NT 256
#define TB 128
#define KDIM 160
#define RS 168           // k-stride (elements) for A/B smem tiles

// smem byte offsets
#define OFF_AHI 0
#define OFF_ALO 43008
#define OFF_B   86016    // [buf][hi/lo][64][RS] bf16 : 4 x 21504
#define OFF_QIN 172032   // float [2][128][4]
#define OFF_B1  176128   // float [2][256]
#define OFF_W2T 178176   // float [2][256][4]
#define OFF_B2  186368
#define OFF_TRC 186400
#define OFF_TRS 186592
#define OFF_PP  186784
#define SMEM_BYTES 186800

#define BCH 21504        // bytes per (buf,hi/lo) B chunk

// W1 pre-split into bf16 hi/lo, [br][n][RS]
__device__ __align__(16) __nv_bfloat16 g_W1hi[2][256][RS];
__device__ __align__(16) __nv_bfloat16 g_W1lo[2][256][RS];

__device__ __forceinline__ uint32_t smem_u32(const void* p) {
    uint32_t a;
    asm("{ .reg .u64 t; cvta.to.shared.u64 t, %1; cvt.u32.u64 %0, t; }" : "=r"(a) : "l"(p));
    return a;
}
__device__ __forceinline__ void mma_bf16(float (&d)[4], const uint32_t (&a)[4],
                                         uint32_t b0, uint32_t b1) {
    asm volatile(
        "mma.sync.aligned.m16n8k16.row.col.f32.bf16.bf16.f32 "
        "{%0,%1,%2,%3}, {%4,%5,%6,%7}, {%8,%9}, {%0,%1,%2,%3};"
        : "+f"(d[0]), "+f"(d[1]), "+f"(d[2]), "+f"(d[3])
        : "r"(a[0]), "r"(a[1]), "r"(a[2]), "r"(a[3]), "r"(b0), "r"(b1));
}
__device__ __forceinline__ void ldsm4(uint32_t (&r)[4], uint32_t addr) {
    asm volatile("ldmatrix.sync.aligned.m8n8.x4.shared.b16 {%0,%1,%2,%3}, [%4];"
        : "=r"(r[0]), "=r"(r[1]), "=r"(r[2]), "=r"(r[3]) : "r"(addr));
}
#define CPA16(dst, src) asm volatile("cp.async.cg.shared.global [%0], [%1], 16;" :: "r"(dst), "l"(src))
#define CPA_COMMIT()    asm volatile("cp.async.commit_group;")
#define CPA_WAIT1()     asm volatile("cp.async.wait_group 1;")
#define CPA_WAIT0()     asm volatile("cp.async.wait_group 0;")

// ---------------- quantum gates on 16-amplitude register state ----------------
template<int M>
__device__ __forceinline__ void g_ry(float (&ar)[16], float (&ai)[16], float c, float s) {
#pragma unroll
    for (int i = 0; i < 16; i++) if (!(i & M)) {
        const int j = i | M;
        float xr = ar[i], xi = ai[i], yr = ar[j], yi = ai[j];
        ar[i] = c * xr - s * yr;  ai[i] = c * xi - s * yi;
        ar[j] = s * xr + c * yr;  ai[j] = s * xi + c * yi;
    }
}
template<int M>
__device__ __forceinline__ void g_rx(float (&ar)[16], float (&ai)[16], float c, float s) {
#pragma unroll
    for (int i = 0; i < 16; i++) if (!(i & M)) {
        const int j = i | M;
        float xr = ar[i], xi = ai[i], yr = ar[j], yi = ai[j];
        ar[i] = c * xr + s * yi;   ai[i] = c * xi - s * yr;
        ar[j] = s * xi + c * yr;   ai[j] = -s * xr + c * yi;
    }
}
template<int M>
__device__ __forceinline__ void g_rz(float (&ar)[16], float (&ai)[16], float c, float s) {
#pragma unroll
    for (int i = 0; i < 16; i++) if (!(i & M)) {
        const int j = i | M;
        float xr = ar[i], xi = ai[i], yr = ar[j], yi = ai[j];
        ar[i] = c * xr + s * xi;   ai[i] = c * xi - s * xr;
        ar[j] = c * yr - s * yi;   ai[j] = c * yi + s * yr;
    }
}
template<int MC, int MT>
__device__ __forceinline__ void g_cnot(float (&ar)[16], float (&ai)[16]) {
#pragma unroll
    for (int i = 0; i < 16; i++) if ((i & MC) && !(i & MT)) {
        const int j = i | MT;
        float tr = ar[i]; ar[i] = ar[j]; ar[j] = tr;
        float ti = ai[i]; ai[i] = ai[j]; ai[j] = ti;
    }
}

// ---------------- prep: W1 -> bf16 hi/lo ----------------
__global__ void qprep(const float* __restrict__ W1a, const float* __restrict__ W1b) {
    const int t = blockIdx.x * 256 + threadIdx.x;    // 0..20479
    const int br = t / 10240;
    const int rem = t % 10240;
    const int n = rem / 40, k4 = rem % 40;
    const float4 v = *(const float4*)((br ? W1b : W1a) + (size_t)n * KDIM + k4 * 4);
    const float vals[4] = {v.x, v.y, v.z, v.w};
#pragma unroll
    for (int j = 0; j < 4; j++) {
        const __nv_bfloat16 h = __float2bfloat16(vals[j]);
        g_W1hi[br][n][k4 * 4 + j] = h;
        g_W1lo[br][n][k4 * 4 + j] = __float2bfloat16(vals[j] - __bfloat162float(h));
    }
}

// ---------------- main kernel ----------------
__global__ __launch_bounds__(NT, 1)
void qmain(const float* __restrict__ state, const float* __restrict__ action,
           const float* __restrict__ b1a, const float* __restrict__ W2a, const float* __restrict__ b2a,
           const float* __restrict__ b1b, const float* __restrict__ W2b, const float* __restrict__ b2b,
           const float* __restrict__ qwa, const float* __restrict__ qwb,
           const float* __restrict__ pwa, const float* __restrict__ pba,
           const float* __restrict__ pwb, const float* __restrict__ pbb,
           float* __restrict__ out, int Btot)
{
    extern __shared__ __align__(16) unsigned char smp[];
    float* smf = (float*)smp;
    __nv_bfloat16* Ahi = (__nv_bfloat16*)(smp + OFF_AHI);
    __nv_bfloat16* Alo = (__nv_bfloat16*)(smp + OFF_ALO);
    float* qin = smf + OFF_QIN / 4;
    const uint32_t smb = smem_u32(smp);

    const int tid = threadIdx.x;
    const int lane = tid & 31, w = tid >> 5;
    const int gid = lane >> 2, tig = lane & 3;
    const int wm = w & 3, wn = w >> 2;
    const int m0 = wm * 32, n0 = wn * 32;
    const int rowg0 = blockIdx.x * TB;

    // ---- kick off B loads for pass 0 (buf 0) ----
    {
        const char* srcH = (const char*)&g_W1hi[0][0][0];
        const char* srcL = (const char*)&g_W1lo[0][0][0];
        for (int i = tid; i < BCH / 16; i += NT) {
            CPA16(smb + OFF_B + i * 16, srcH + i * 16);
            CPA16(smb + OFF_B + BCH + i * 16, srcL + i * 16);
        }
        CPA_COMMIT();
    }

    // ---- params into smem ----
    for (int i = tid; i < 512; i += NT)
        smf[OFF_B1 / 4 + i] = ((i >> 8) ? b1b : b1a)[i & 255];
    for (int i = tid; i < 2048; i += NT) {
        const int br = i >> 10, rem = i & 1023, n = rem >> 2, q = rem & 3;
        smf[OFF_W2T / 4 + i] = (br ? W2b : W2a)[q * 256 + n];
    }
    if (tid < 8)  smf[OFF_B2 / 4 + tid] = ((tid >> 2) ? b2b : b2a)[tid & 3];
    if (tid < 48) {
        const int br = tid / 24, g = tid % 24;
        float sv, cv;
        sincosf(0.5f * (br ? qwb : qwa)[g], &sv, &cv);
        smf[OFF_TRC / 4 + tid] = cv;  smf[OFF_TRS / 4 + tid] = sv;
    }
    if (tid < 4)
        smf[OFF_PP / 4 + tid] = (tid == 0) ? pwa[0] : (tid == 1) ? pba[0]
                               : (tid == 2) ? pwb[0] : pbb[0];
    for (int i = tid; i < 1024; i += NT) qin[i] = 0.f;

    // ---- x -> A hi/lo smem [row][k], stride RS ----
    {
        const int r = tid >> 1, hf = tid & 1;
        const float* srow = state  + (size_t)(rowg0 + r) * 128;
        const float* arow = action + (size_t)(rowg0 + r) * 32;
#pragma unroll 5
        for (int i = 0; i < 20; i++) {
            const int k = hf * 80 + i * 4;
            const float4 v = (k < 128) ? *(const float4*)(srow + k)
                                       : *(const float4*)(arow + (k - 128));
            const float vals[4] = {v.x, v.y, v.z, v.w};
#pragma unroll
            for (int p = 0; p < 2; p++) {
                const float a = vals[p * 2], b = vals[p * 2 + 1];
                const __nv_bfloat16 ha = __float2bfloat16(a), hb = __float2bfloat16(b);
                *(__nv_bfloat162*)(Ahi + r * RS + k + p * 2) = __halves2bfloat162(ha, hb);
                *(__nv_bfloat162*)(Alo + r * RS + k + p * 2) =
                    __halves2bfloat162(__float2bfloat16(a - __bfloat162float(ha)),
                                       __float2bfloat16(b - __bfloat162float(hb)));
            }
        }
    }

    // ---- ldmatrix byte-address bases ----
    const uint32_t aB0h = smb + OFF_AHI + (uint32_t)((m0 + (lane & 15)) * RS + 8 * (lane >> 4)) * 2;
    const uint32_t aB1h = aB0h + 16u * RS * 2;
    const uint32_t aB0l = aB0h + (OFF_ALO - OFF_AHI);
    const uint32_t aB1l = aB1h + (OFF_ALO - OFF_AHI);
    const uint32_t bOff0 = (uint32_t)((n0 + 8 * (lane >> 4) + (lane & 7)) * RS
                                      + 8 * ((lane >> 3) & 1)) * 2;
    const uint32_t bOff1 = bOff0 + 16u * RS * 2;

    // per-row W2 partials, accumulated across the 4 passes of each branch
    float p0[4] = {0.f, 0.f, 0.f, 0.f}, p1[4] = {0.f, 0.f, 0.f, 0.f};

#pragma unroll 1
    for (int pass = 0; pass < 8; pass++) {
        const int br = pass >> 2, chunk = pass & 3;
        const int nbase = chunk * 64;
        const int buf = pass & 1;

        // issue B loads for next pass into the other buffer
        if (pass < 7) {
            const int pN = pass + 1;
            const char* srcH = (const char*)&g_W1hi[pN >> 2][(pN & 3) * 64][0];
            const char* srcL = (const char*)&g_W1lo[pN >> 2][(pN & 3) * 64][0];
            const uint32_t dst = smb + OFF_B + (uint32_t)(pN & 1) * (2 * BCH);
            for (int i = tid; i < BCH / 16; i += NT) {
                CPA16(dst + i * 16, srcH + i * 16);
                CPA16(dst + BCH + i * 16, srcL + i * 16);
            }
            CPA_COMMIT();
            CPA_WAIT1();
        } else {
            CPA_WAIT0();
        }
        __syncthreads();   // current buf ready for all warps

        const uint32_t bhB = smb + OFF_B + (uint32_t)buf * (2 * BCH);
        const uint32_t blB = bhB + BCH;

        float acc[2][4][4];
#pragma unroll
        for (int mf = 0; mf < 2; mf++)
#pragma unroll
            for (int nf = 0; nf < 4; nf++)
#pragma unroll
                for (int c = 0; c < 4; c++) acc[mf][nf][c] = 0.f;

        // ---- fully-unrolled, fragment-double-buffered, term-major mainloop ----
        uint32_t fah[2][2][4], fal[2][2][4], fbh[2][2][4], fbl[2][2][4];

#define LDFRAG(b, k0b)                                                    \
        do {                                                              \
            ldsm4(fah[b][0], aB0h + (k0b));                               \
            ldsm4(fah[b][1], aB1h + (k0b));                               \
            ldsm4(fal[b][0], aB0l + (k0b));                               \
            ldsm4(fal[b][1], aB1l + (k0b));                               \
            ldsm4(fbh[b][0], bhB + bOff0 + (k0b));                        \
            ldsm4(fbh[b][1], bhB + bOff1 + (k0b));                        \
            ldsm4(fbl[b][0], blB + bOff0 + (k0b));                        \
            ldsm4(fbl[b][1], blB + bOff1 + (k0b));                        \
        } while (0)

        LDFRAG(0, 0u);
#pragma unroll
        for (int ks = 0; ks < 10; ks++) {
            const int cur = ks & 1, nxt = cur ^ 1;
            if (ks < 9) LDFRAG(nxt, (uint32_t)((ks + 1) * 32));  // 16 elem * 2B
            // term-major: same-acc reuse distance = 8 MMA issues
#pragma unroll
            for (int t = 0; t < 3; t++)
#pragma unroll
                for (int p = 0; p < 2; p++)
#pragma unroll
                    for (int q = 0; q < 2; q++)
#pragma unroll
                        for (int mf = 0; mf < 2; mf++) {
                            const uint32_t (&a4)[4] = (t == 1) ? fal[cur][mf] : fah[cur][mf];
                            const uint32_t b0 = (t == 2) ? fbl[cur][p][q * 2]     : fbh[cur][p][q * 2];
                            const uint32_t b1 = (t == 2) ? fbl[cur][p][q * 2 + 1] : fbh[cur][p][q * 2 + 1];
                            mma_bf16(acc[mf][p * 2 + q], a4, b0, b1);
                        }
        }
#undef LDFRAG

        // ---- bias + relu + W2 contraction into register partials ----
        const float* b1s = smf + OFF_B1 / 4 + br * 256;
        const float* w2t = smf + OFF_W2T / 4 + br * 1024;
#pragma unroll
        for (int mf = 0; mf < 2; mf++) {
            float* pp = mf ? p1 : p0;
#pragma unroll
            for (int nf = 0; nf < 4; nf++)
#pragma unroll
                for (int c = 0; c < 2; c++) {
                    const int gcol = nbase + n0 + nf * 8 + 2 * tig + c;
                    const float bb = b1s[gcol];
                    const float h0 = fmaxf(acc[mf][nf][c] + bb, 0.f);
                    const float h1 = fmaxf(acc[mf][nf][2 + c] + bb, 0.f);
                    const float4 wv = *(const float4*)(w2t + gcol * 4);
                    pp[0] = fmaf(h0, wv.x, pp[0]);  pp[1] = fmaf(h0, wv.y, pp[1]);
                    pp[2] = fmaf(h0, wv.z, pp[2]);  pp[3] = fmaf(h0, wv.w, pp[3]);
                    acc[mf][nf][2 + c] = h1;   // stash post-relu row+8 value
                }
        }
#pragma unroll
        for (int mf = 0; mf < 2; mf++) {
            float s[4] = {0.f, 0.f, 0.f, 0.f};
#pragma unroll
            for (int nf = 0; nf < 4; nf++)
#pragma unroll
                for (int c = 0; c < 2; c++) {
                    const int gcol = nbase + n0 + nf * 8 + 2 * tig + c;
                    const float h1 = acc[mf][nf][2 + c];
                    const float4 wv = *(const float4*)(w2t + gcol * 4);
                    s[0] = fmaf(h1, wv.x, s[0]);  s[1] = fmaf(h1, wv.y, s[1]);
                    s[2] = fmaf(h1, wv.z, s[2]);  s[3] = fmaf(h1, wv.w, s[3]);
                }
#pragma unroll
            for (int off = 1; off <= 2; off <<= 1)
#pragma unroll
                for (int j = 0; j < 4; j++)
                    s[j] += __shfl_xor_sync(0xffffffffu, s[j], off);
            if (tig == 0) {
                float* qdst = qin + ((br << 7) + m0 + mf * 16 + gid + 8) * 4;
#pragma unroll
                for (int j = 0; j < 4; j++) atomicAdd(qdst + j, s[j]);
            }
        }

        // flush p0/p1 at branch boundary
        if (chunk == 3) {
#pragma unroll
            for (int off = 1; off <= 2; off <<= 1)
#pragma unroll
                for (int j = 0; j < 4; j++) {
                    p0[j] += __shfl_xor_sync(0xffffffffu, p0[j], off);
                    p1[j] += __shfl_xor_sync(0xffffffffu, p1[j], off);
                }
            if (tig == 0) {
                float* q0 = qin + ((br << 7) + m0 + gid) * 4;
                float* q1 = qin + ((br << 7) + m0 + 16 + gid) * 4;
#pragma unroll
                for (int j = 0; j < 4; j++) {
                    atomicAdd(q0 + j, p0[j]);
                    atomicAdd(q1 + j, p1[j]);
                }
            }
#pragma unroll
            for (int j = 0; j < 4; j++) { p0[j] = 0.f; p1[j] = 0.f; }
        }

        __syncthreads();   // all reads of buf done before it is overwritten
    }
    __syncthreads();

    // ---- quantum circuit: 1 row/thread, 128 rows x 2 branches ----
    {
        const int br = tid >> 7, row = tid & 127;
        const float* b2s = smf + OFF_B2 / 4 + br * 4;
        const float* trc = smf + OFF_TRC / 4 + br * 24;
        const float* trs = smf + OFF_TRS / 4 + br * 24;
        const float pw = smf[OFF_PP / 4 + br * 2];
        const float pb = smf[OFF_PP / 4 + br * 2 + 1];
        const float* qv = qin + ((br << 7) + row) * 4;
        const float th[4] = {qv[0] + b2s[0], qv[1] + b2s[1], qv[2] + b2s[2], qv[3] + b2s[3]};

        float ar[16], ai[16];
#pragma unroll
        for (int i = 0; i < 16; i++) { ar[i] = 0.f; ai[i] = 0.f; }
        ar[0] = 1.f;

        float s0, c0;
        sincosf(0.5f * th[0], &s0, &c0);  g_ry<8>(ar, ai, c0, s0);
        sincosf(0.5f * th[1], &s0, &c0);  g_ry<4>(ar, ai, c0, s0);
        sincosf(0.5f * th[2], &s0, &c0);  g_ry<2>(ar, ai, c0, s0);
        sincosf(0.5f * th[3], &s0, &c0);  g_ry<1>(ar, ai, c0, s0);

#pragma unroll
        for (int l = 0; l < 2; l++) {
            const int lb = l * 12;
            g_rx<8>(ar, ai, trc[lb + 0],  trs[lb + 0]);
            g_ry<8>(ar, ai, trc[lb + 1],  trs[lb + 1]);
            g_rz<8>(ar, ai, trc[lb + 2],  trs[lb + 2]);
            g_rx<4>(ar, ai, trc[lb + 3],  trs[lb + 3]);
            g_ry<4>(ar, ai, trc[lb + 4],  trs[lb + 4]);
            g_rz<4>(ar, ai, trc[lb + 5],  trs[lb + 5]);
            g_rx<2>(ar, ai, trc[lb + 6],  trs[lb + 6]);
            g_ry<2>(ar, ai, trc[lb + 7],  trs[lb + 7]);
            g_rz<2>(ar, ai, trc[lb + 8],  trs[lb + 8]);
            g_rx<1>(ar, ai, trc[lb + 9],  trs[lb + 9]);
            g_ry<1>(ar, ai, trc[lb + 10], trs[lb + 10]);
            g_rz<1>(ar, ai, trc[lb + 11], trs[lb + 11]);
            g_cnot<8, 4>(ar, ai);
            g_cnot<4, 2>(ar, ai);
            g_cnot<2, 1>(ar, ai);
            g_cnot<1, 8>(ar, ai);
        }

        float ev = 0.f;
#pragma unroll
        for (int i = 0; i < 16; i++) {
            const float p = ar[i] * ar[i] + ai[i] * ai[i];
            ev += (i & 8) ? -p : p;
        }
        out[(size_t)br * Btot + rowg0 + row] = fmaf(ev, pw, pb);
    }
}

extern "C" void kernel_launch(void* const* d_in, const int* in_sizes, int n_in,
                              void* d_out, int out_size)
{
    const int Btot = in_sizes[0] / 128;
    static bool attr_set = false;
    if (!attr_set) {
        cudaFuncSetAttribute(qmain, cudaFuncAttributeMaxDynamicSharedMemorySize, SMEM_BYTES);
        attr_set = true;
    }
    qprep<<<80, 256>>>((const float*)d_in[2], (const float*)d_in[6]);
    qmain<<<Btot / TB, NT, SMEM_BYTES>>>(
        (const float*)d_in[0],  (const float*)d_in[1],
        (const float*)d_in[3],  (const float*)d_in[4],  (const float*)d_in[5],
        (const float*)d_in[7],  (const float*)d_in[8],  (const float*)d_in[9],
        (const float*)d_in[10], (const float*)d_in[11],
        (const float*)d_in[12], (const float*)d_in[13],
        (const float*)d_in[14], (const float*)d_in[15],
        (float*)d_out, Btot);
}